// round 12
// baseline (speedup 1.0000x reference)
#include <cuda_runtime.h>
#include <math.h>

#define T_SEQ 4096
#define NF    2048
#define HID   1024
#define G4    4096
#define NC_DIR 74
#define NCTA  (2*NC_DIR)
#define NTAGS 10
#define START_TAG 8
#define STOP_TAG  9

// Recurrence: warp w owns hidden units j = w and j = w+8 (if < nh).
// Rows rid: 0..3 = gates i,f,g,o of j1=w (registers), 4 = gate i of j2 (reg),
// 5..7 = gates f,g,o of j2 (SMEM).
#define REG_ROWS  5
#define SMEM_ROWS 24                       // 8 warps x 3 rows
#define REC_SMEM  (128 * 1024)             // pad -> exactly 1 CTA/SM

#define VIT_SMEM  (T_SEQ*NTAGS*4 + T_SEQ*NTAGS + T_SEQ)

// GEMM smem row pitch (floats): pad 128->132 to cut staging-store conflicts
#define LDA 132

// ---------------- scratch -----------------------------------------------------
__device__ __align__(16) float g_xp[2][(size_t)T_SEQ * G4];
__device__ __align__(16) float g_hs[(size_t)T_SEQ * 2048];
__device__ __align__(16) float g_feats[T_SEQ * NTAGS];
__device__ unsigned int g_ctrs[128];       // [0]=fwd, [64]=bwd (256B apart)

// ---------------- helpers -----------------------------------------------------
__device__ __forceinline__ unsigned int ld_acquire_u32(const unsigned int* p) {
    unsigned int v;
    asm volatile("ld.acquire.gpu.u32 %0, [%1];" : "=r"(v) : "l"(p) : "memory");
    return v;
}
__device__ __forceinline__ void red_release_add(unsigned int* p, unsigned int v) {
    asm volatile("red.release.gpu.global.add.u32 [%0], %1;" :: "l"(p), "r"(v) : "memory");
}
__device__ __forceinline__ unsigned int atom_acqrel_cta_add(unsigned int* p, unsigned int v) {
    unsigned int old;
    asm volatile("atom.acq_rel.cta.add.u32 %0, [%1], %2;"
                 : "=r"(old) : "l"(p), "r"(v) : "memory");
    return old;
}
__device__ __forceinline__ unsigned long long ffma2(unsigned long long a,
                                                    unsigned long long b,
                                                    unsigned long long c) {
    unsigned long long d;
    asm("fma.rn.f32x2 %0, %1, %2, %3;" : "=l"(d) : "l"(a), "l"(b), "l"(c));
    return d;
}
__device__ __forceinline__ unsigned long long splat2(float x) {
    unsigned long long d;
    asm("mov.b64 %0, {%1, %1};" : "=l"(d) : "f"(x));
    return d;
}
__device__ __forceinline__ float lo2(unsigned long long v) {
    return __uint_as_float((unsigned int)(v & 0xffffffffull));
}
__device__ __forceinline__ float hi2(unsigned long long v) {
    return __uint_as_float((unsigned int)(v >> 32));
}
__device__ __forceinline__ float hsum2(unsigned long long v) { return lo2(v) + hi2(v); }
__device__ __forceinline__ float fast_sig(float x) {
    return __fdividef(1.0f, 1.0f + __expf(-x));
}
__device__ __forceinline__ float fast_tanh(float x) {
    float e = __expf(2.0f * x);
    return 1.0f - __fdividef(2.0f, e + 1.0f);
}

__global__ void ctr_init_kernel() { g_ctrs[0] = 0u; g_ctrs[64] = 0u; }
__global__ void nop_kernel() {}

// ---------------- input projection GEMM --------------------------------------
// Conflict-free inner loop: per k-slice each thread does 2x LDS.128 (a8) +
// 2x LDS.128 (b8) of contiguous 32B (lanes stride 32B -> no conflicts),
// 8 register splats, 32 FFMA2.
__global__ void __launch_bounds__(256, 2) xp_gemm_kernel(
    const float* __restrict__ A,
    const float* __restrict__ Wf, const float* __restrict__ Wb,
    const float* __restrict__ bf, const float* __restrict__ bb)
{
    __shared__ float As[16 * LDA];
    __shared__ float Bs[16 * LDA];

    const int dir = blockIdx.z;
    const float* __restrict__ B    = dir ? Wb : Wf;
    const float* __restrict__ bias = dir ? bb : bf;
    float* __restrict__ C = g_xp[dir];

    const int tid = threadIdx.x;
    const int tx = tid & 15, ty = tid >> 4;
    const int m0 = blockIdx.y * 128, n0 = blockIdx.x * 128;
    const int lr = tid >> 2;
    const int lc = (tid & 3) * 4;

    unsigned long long acc2[4][8];
#pragma unroll
    for (int ip = 0; ip < 4; ip++)
#pragma unroll
        for (int j = 0; j < 8; j++) acc2[ip][j] = 0ull;

    for (int k0 = 0; k0 < NF; k0 += 16) {
        float4 a0 = *reinterpret_cast<const float4*>(&A[(size_t)(m0 + lr)      * NF + k0 + lc]);
        float4 a1 = *reinterpret_cast<const float4*>(&A[(size_t)(m0 + lr + 64) * NF + k0 + lc]);
        float4 b0 = *reinterpret_cast<const float4*>(&B[(size_t)(n0 + lr)      * NF + k0 + lc]);
        float4 b1 = *reinterpret_cast<const float4*>(&B[(size_t)(n0 + lr + 64) * NF + k0 + lc]);
        __syncthreads();
        As[(lc + 0) * LDA + lr] = a0.x; As[(lc + 1) * LDA + lr] = a0.y;
        As[(lc + 2) * LDA + lr] = a0.z; As[(lc + 3) * LDA + lr] = a0.w;
        As[(lc + 0) * LDA + lr + 64] = a1.x; As[(lc + 1) * LDA + lr + 64] = a1.y;
        As[(lc + 2) * LDA + lr + 64] = a1.z; As[(lc + 3) * LDA + lr + 64] = a1.w;
        Bs[(lc + 0) * LDA + lr] = b0.x; Bs[(lc + 1) * LDA + lr] = b0.y;
        Bs[(lc + 2) * LDA + lr] = b0.z; Bs[(lc + 3) * LDA + lr] = b0.w;
        Bs[(lc + 0) * LDA + lr + 64] = b1.x; Bs[(lc + 1) * LDA + lr + 64] = b1.y;
        Bs[(lc + 2) * LDA + lr + 64] = b1.z; Bs[(lc + 3) * LDA + lr + 64] = b1.w;
        __syncthreads();
#pragma unroll
        for (int k = 0; k < 16; k++) {
            // a8: rows ty*8..+7 as 4 fp32x2 pairs (contiguous 32B, LDS.128 x2)
            ulonglong2 ap01 = *reinterpret_cast<const ulonglong2*>(&As[k * LDA + ty * 8]);
            ulonglong2 ap23 = *reinterpret_cast<const ulonglong2*>(&As[k * LDA + ty * 8 + 4]);
            unsigned long long ap[4] = {ap01.x, ap01.y, ap23.x, ap23.y};
            // b8: cols tx*8..+7 (contiguous 32B, LDS.128 x2)
            float4 bv0 = *reinterpret_cast<const float4*>(&Bs[k * LDA + tx * 8]);
            float4 bv1 = *reinterpret_cast<const float4*>(&Bs[k * LDA + tx * 8 + 4]);
            float bvals[8] = {bv0.x, bv0.y, bv0.z, bv0.w, bv1.x, bv1.y, bv1.z, bv1.w};
#pragma unroll
            for (int j = 0; j < 8; j++) {
                unsigned long long bb2 = splat2(bvals[j]);
#pragma unroll
                for (int ip = 0; ip < 4; ip++)
                    acc2[ip][j] = ffma2(ap[ip], bb2, acc2[ip][j]);
            }
        }
    }

#pragma unroll
    for (int ip = 0; ip < 4; ip++) {
        size_t row0 = (size_t)(m0 + ty * 8 + 2 * ip) * G4 + n0 + tx * 8;
        size_t row1 = row0 + G4;
#pragma unroll
        for (int j = 0; j < 8; j++) {
            float bj = bias[n0 + tx * 8 + j];
            C[row0 + j] = lo2(acc2[ip][j]) + bj;
            C[row1 + j] = hi2(acc2[ip][j]) + bj;
        }
    }
}

// ---------------- persistent recurrence kernel -------------------------------
// Warp w owns hidden units j1=w, j2=w+8 (if < nh). After the warp reduce,
// lanes 0/1 compute gates for j1/j2 with c in registers. CTA completion via
// SMEM acq_rel counter; 8th warp issues the gpu-release RED.
__global__ void __launch_bounds__(256, 1) lstm_rec_kernel(
    const float* __restrict__ Whf, const float* __restrict__ Whb)
{
    extern __shared__ float smem[];
    float* ws = smem;                          // [SMEM_ROWS][1024]
    __shared__ unsigned int scnt;

    const int blk = blockIdx.x;
    const int dir = blk / NC_DIR;
    const int r   = blk % NC_DIR;
    const int h0 = (r * HID) / NC_DIR;
    const int h1 = ((r + 1) * HID) / NC_DIR;
    const int nh = h1 - h0;                    // 13 or 14
    const float* __restrict__ W = dir ? Whb : Whf;
    const int tid = threadIdx.x;
    const int lane = tid & 31, warp = tid >> 5;
    const bool has_j2 = (warp + 8) < nh;

    // register rows: rid 0..3 -> gates 0..3 of j1=w; rid 4 -> gate 0 of j2
    ulonglong2 wreg[REG_ROWS][8];
#pragma unroll
    for (int i = 0; i < REG_ROWS; i++) {
        int g = (i < 4) ? i : 0;
        int j = (i < 4) ? warp : (warp + 8);
        const float* wr = (j < nh) ? &W[(size_t)(g * HID + h0 + j) * HID] : W;
#pragma unroll
        for (int k = 0; k < 8; k++)
            wreg[i][k] = *reinterpret_cast<const ulonglong2*>(wr + 4 * lane + 128 * k);
    }
    // SMEM rows: slot = w2*3 + s  <->  gate (1+s) of j2 = w2+8
    for (int idx = tid; idx < SMEM_ROWS * 256; idx += 256) {
        int slot = idx >> 8;
        int c4 = (idx & 255) * 4;
        int w2 = slot / 3;
        int g = 1 + slot % 3;
        int j = w2 + 8;
        const float* wr = (j < nh) ? &W[(size_t)(g * HID + h0 + j) * HID] : W;
        *reinterpret_cast<float4*>(&ws[(size_t)slot * HID + c4]) =
            *reinterpret_cast<const float4*>(wr + c4);
    }
    if (tid == 0) scnt = 0u;
    __syncthreads();

    unsigned int* ctr = &g_ctrs[dir * 64];

    // per-lane gate state: lane 0 -> j1, lane 1 -> j2
    const int jown = warp + 8 * lane;                    // valid for lane<2
    const bool own = (lane < 2) && (jown < nh);
    float cst = 0.0f;

    for (int step = 0; step < T_SEQ; ++step) {
        const int t = dir ? (T_SEQ - 1 - step) : step;

        // xp prefetch for owned unit (independent of h_prev)
        float xi = 0.f, xf = 0.f, xg = 0.f, xo = 0.f;
        if (own) {
            const float* xp = &g_xp[dir][(size_t)t * G4 + h0 + jown];
            xi = __ldg(&xp[0]);
            xf = __ldg(&xp[HID]);
            xg = __ldg(&xp[2 * HID]);
            xo = __ldg(&xp[3 * HID]);
        }

        float a[8];
#pragma unroll
        for (int i = 0; i < 8; i++) a[i] = 0.0f;

        if (step > 0) {
            if (tid == 0) {
                const unsigned int target = (unsigned int)(NC_DIR * step);
                while (ld_acquire_u32(ctr) < target) { }
            }
            __syncthreads();   // also publishes scnt reset from prior step

            const float* hp = &g_hs[(size_t)(dir ? t + 1 : t - 1) * 2048 + dir * HID];
            ulonglong2 h2[8];
#pragma unroll
            for (int k = 0; k < 8; k++)
                h2[k] = __ldcg(reinterpret_cast<const ulonglong2*>(hp + 4 * lane + 128 * k));

#pragma unroll
            for (int i = 0; i < REG_ROWS; i++) {
                unsigned long long s0 = 0ull, s1 = 0ull;
#pragma unroll
                for (int k = 0; k < 8; k++) {
                    s0 = ffma2(wreg[i][k].x, h2[k].x, s0);
                    s1 = ffma2(wreg[i][k].y, h2[k].y, s1);
                }
                a[i] = hsum2(s0) + hsum2(s1);
            }
            if (has_j2) {
#pragma unroll
                for (int s = 0; s < 3; s++) {
                    const float* base = &ws[(size_t)(warp * 3 + s) * HID + 4 * lane];
                    unsigned long long s0 = 0ull, s1 = 0ull;
#pragma unroll
                    for (int k = 0; k < 8; k++) {
                        ulonglong2 w2 = *reinterpret_cast<const ulonglong2*>(base + 128 * k);
                        s0 = ffma2(w2.x, h2[k].x, s0);
                        s1 = ffma2(w2.y, h2[k].y, s1);
                    }
                    a[5 + s] = hsum2(s0) + hsum2(s1);
                }
            }
#pragma unroll
            for (int off = 16; off > 0; off >>= 1)
#pragma unroll
                for (int i = 0; i < 8; i++)
                    a[i] += __shfl_xor_sync(0xffffffffu, a[i], off);
        }

        // gates: lane0 uses a[0..3] (j1), lane1 uses a[4],a[5..7] (j2)
        if (own) {
            float pi, pf, pg, po;
            if (lane == 0) { pi = a[0]; pf = a[1]; pg = a[2]; po = a[3]; }
            else           { pi = a[4]; pf = a[5]; pg = a[6]; po = a[7]; }
            pi += xi; pf += xf; pg += xg; po += xo;
            float c = fast_sig(pf) * cst + fast_sig(pi) * fast_tanh(pg);
            cst = c;
            float h = fast_sig(po) * fast_tanh(c);
            g_hs[(size_t)t * 2048 + dir * HID + h0 + jown] = h;
        }
        __syncwarp();
        if (lane == 0) {
            unsigned int prev = atom_acqrel_cta_add(&scnt, 1u);
            if (prev == 7u) {              // last warp: all 8 warps' h stores chained in
                scnt = 0u;
                red_release_add(ctr, 1u);
            }
        }
    }
}

// ---------------- feats -------------------------------------------------------
__global__ void feats_kernel(const float* __restrict__ Wlin, const float* __restrict__ blin)
{
    const int t = blockIdx.x;
    const int warp = threadIdx.x >> 5;
    const int lane = threadIdx.x & 31;
    const float* h = &g_hs[(size_t)t * 2048];
    const float* w = &Wlin[(size_t)warp * 2048];
    float a0 = 0.f, a1 = 0.f, a2 = 0.f, a3 = 0.f;
#pragma unroll
    for (int k = 0; k < 16; k++) {
        float4 hv = *reinterpret_cast<const float4*>(h + 4 * lane + 128 * k);
        float4 wv = __ldg(reinterpret_cast<const float4*>(w + 4 * lane + 128 * k));
        a0 += hv.x * wv.x; a1 += hv.y * wv.y; a2 += hv.z * wv.z; a3 += hv.w * wv.w;
    }
    float a = (a0 + a1) + (a2 + a3);
#pragma unroll
    for (int off = 16; off > 0; off >>= 1)
        a += __shfl_xor_sync(0xffffffffu, a, off);
    if (lane == 0) g_feats[t * NTAGS + warp] = a + blin[warp];
}

// ---------------- Viterbi -----------------------------------------------------
__global__ void __launch_bounds__(256, 1) viterbi_kernel(
    const float* __restrict__ trans, float* __restrict__ out)
{
    extern __shared__ char vsm[];
    float* sf = (float*)vsm;
    unsigned char* bps  = (unsigned char*)(vsm + T_SEQ * NTAGS * 4);
    unsigned char* path = bps + T_SEQ * NTAGS;

    const int nv4 = T_SEQ * NTAGS / 4;
    for (int idx = threadIdx.x; idx < nv4; idx += 256)
        reinterpret_cast<float4*>(sf)[idx] = reinterpret_cast<const float4*>(g_feats)[idx];
    __syncthreads();

    if (threadIdx.x < 32) {
        const int lane = threadIdx.x;
        float trow[NTAGS];
        float fv;
        if (lane < NTAGS) {
#pragma unroll
            for (int i = 0; i < NTAGS; i++) trow[i] = trans[lane * NTAGS + i];
            fv = (lane == START_TAG) ? 0.0f : -10000.0f;
        } else {
#pragma unroll
            for (int i = 0; i < NTAGS; i++) trow[i] = 0.0f;
            fv = -1e30f;
        }

        for (int t = 0; t < T_SEQ; t++) {
            float feat = (lane < NTAGS) ? sf[t * NTAGS + lane] : 0.0f;
            float best = -3.0e38f; int bi = 0;
#pragma unroll
            for (int i = 0; i < NTAGS; i++) {
                float v = __shfl_sync(0xffffffffu, fv, i) + trow[i];
                if (v > best) { best = v; bi = i; }   // first-max tie rule
            }
            if (lane < NTAGS) bps[t * NTAGS + lane] = (unsigned char)bi;
            fv = best + feat;
        }

        float term = (lane < NTAGS) ? (fv + trans[STOP_TAG * NTAGS + lane]) : -3.0e38f;
        float bsc = -3.0e38f; int bidx = 0;
#pragma unroll
        for (int i = 0; i < NTAGS; i++) {
            float v = __shfl_sync(0xffffffffu, term, i);
            if (v > bsc) { bsc = v; bidx = i; }
        }

        if (lane == 0) {
            out[0] = bsc;
            int cur = bidx;
            path[T_SEQ - 1] = (unsigned char)cur;
            for (int t = T_SEQ - 2; t >= 0; --t) {
                cur = bps[(t + 1) * NTAGS + cur];
                path[t] = (unsigned char)cur;
            }
        }
        __syncwarp();
        for (int t = lane; t < T_SEQ; t += 32) out[1 + t] = (float)path[t];
    }
}

// ---------------- launch ------------------------------------------------------
extern "C" void kernel_launch(void* const* d_in, const int* in_sizes, int n_in,
                              void* d_out, int out_size)
{
    const float* sentence = (const float*)d_in[0];
    const float* W_ih_f   = (const float*)d_in[1];
    const float* W_hh_f   = (const float*)d_in[2];
    const float* b_f      = (const float*)d_in[3];
    const float* W_ih_b   = (const float*)d_in[4];
    const float* W_hh_b   = (const float*)d_in[5];
    const float* b_b      = (const float*)d_in[6];
    const float* W_lin    = (const float*)d_in[7];
    const float* b_lin    = (const float*)d_in[8];
    const float* trans    = (const float*)d_in[9];
    float* out = (float*)d_out;

    cudaFuncSetAttribute((const void*)lstm_rec_kernel,
                         cudaFuncAttributeMaxDynamicSharedMemorySize, REC_SMEM);
    cudaFuncSetAttribute((const void*)viterbi_kernel,
                         cudaFuncAttributeMaxDynamicSharedMemorySize, VIT_SMEM);

    // captured profile = 4th launch -> aim it at xp_gemm_kernel
    ctr_init_kernel<<<1, 1>>>();
    nop_kernel<<<1, 1>>>();
    nop_kernel<<<1, 1>>>();

    dim3 gg(G4 / 128, T_SEQ / 128, 2);
    xp_gemm_kernel<<<gg, 256>>>(sentence, W_ih_f, W_ih_b, b_f, b_b);

    lstm_rec_kernel<<<NCTA, 256, REC_SMEM>>>(W_hh_f, W_hh_b);

    feats_kernel<<<T_SEQ, NTAGS * 32>>>(W_lin, b_lin);

    viterbi_kernel<<<1, 256, VIT_SMEM>>>(trans, out);

    (void)in_sizes; (void)n_in; (void)out_size;
}

// round 14
// speedup vs baseline: 1.0861x; 1.0861x over previous
#include <cuda_runtime.h>
#include <math.h>

#define T_SEQ 4096
#define NF    2048
#define HID   1024
#define G4    4096
#define NC_DIR 74
#define NCTA  (2*NC_DIR)
#define NTAGS 10
#define START_TAG 8
#define STOP_TAG  9

// Recurrence (R8 topology): up to 14 hidden units/CTA -> 56 gate rows, 7/warp.
// Rows i=0..4 register-resident (f32x2-packed), i=5..6 in SMEM.
#define RPW       7
#define REG_ROWS  5
#define SMEM_ROWS 16                       // rows 40..55
#define REC_SMEM  (128 * 1024)             // pad -> exactly 1 CTA/SM

#define VIT_SMEM  (T_SEQ*NTAGS*4 + T_SEQ*NTAGS + T_SEQ)

// GEMM smem row pitch: 132 floats -> staging stores conflict-free
#define LDA 132

// ---------------- scratch -----------------------------------------------------
__device__ __align__(16) float g_xp[2][(size_t)T_SEQ * G4];
__device__ __align__(16) float g_hs[(size_t)T_SEQ * 2048];
__device__ __align__(16) float g_feats[T_SEQ * NTAGS];
__device__ unsigned int g_ctrs[128];       // [0]=fwd, [64]=bwd (256B apart)

// ---------------- helpers -----------------------------------------------------
__device__ __forceinline__ unsigned int ld_acquire_u32(const unsigned int* p) {
    unsigned int v;
    asm volatile("ld.acquire.gpu.u32 %0, [%1];" : "=r"(v) : "l"(p) : "memory");
    return v;
}
__device__ __forceinline__ void red_release_add(unsigned int* p, unsigned int v) {
    asm volatile("red.release.gpu.global.add.u32 [%0], %1;" :: "l"(p), "r"(v) : "memory");
}
__device__ __forceinline__ unsigned long long ffma2(unsigned long long a,
                                                    unsigned long long b,
                                                    unsigned long long c) {
    unsigned long long d;
    asm("fma.rn.f32x2 %0, %1, %2, %3;" : "=l"(d) : "l"(a), "l"(b), "l"(c));
    return d;
}
__device__ __forceinline__ unsigned long long splat2(float x) {
    unsigned long long d;
    asm("mov.b64 %0, {%1, %1};" : "=l"(d) : "f"(x));
    return d;
}
__device__ __forceinline__ float lo2(unsigned long long v) {
    return __uint_as_float((unsigned int)(v & 0xffffffffull));
}
__device__ __forceinline__ float hi2(unsigned long long v) {
    return __uint_as_float((unsigned int)(v >> 32));
}
__device__ __forceinline__ float hsum2(unsigned long long v) { return lo2(v) + hi2(v); }
__device__ __forceinline__ float fast_sig(float x) {
    return __fdividef(1.0f, 1.0f + __expf(-x));
}
__device__ __forceinline__ float fast_tanh(float x) {
    float e = __expf(2.0f * x);
    return 1.0f - __fdividef(2.0f, e + 1.0f);
}

__global__ void ctr_init_kernel() { g_ctrs[0] = 0u; g_ctrs[64] = 0u; }
__global__ void nop_kernel() {}

// ---------------- input projection GEMM --------------------------------------
// 128x128x16 tile, FFMA2 accumulators. Staging stores conflict-free (LDA=132);
// fragment loads: a8 = 2x LDS.128 broadcast, b8 = 2x LDS.128 (4-way max).
__global__ void __launch_bounds__(256, 2) xp_gemm_kernel(
    const float* __restrict__ A,
    const float* __restrict__ Wf, const float* __restrict__ Wb,
    const float* __restrict__ bf, const float* __restrict__ bb)
{
    __shared__ float As[16 * LDA];
    __shared__ float Bs[16 * LDA];

    const int dir = blockIdx.z;
    const float* __restrict__ B    = dir ? Wb : Wf;
    const float* __restrict__ bias = dir ? bb : bf;
    float* __restrict__ C = g_xp[dir];

    const int tid = threadIdx.x;
    const int tx = tid & 15, ty = tid >> 4;
    const int m0 = blockIdx.y * 128, n0 = blockIdx.x * 128;
    const int lr = tid >> 2;
    const int lc = (tid & 3) * 4;

    unsigned long long acc2[4][8];
#pragma unroll
    for (int ip = 0; ip < 4; ip++)
#pragma unroll
        for (int j = 0; j < 8; j++) acc2[ip][j] = 0ull;

    for (int k0 = 0; k0 < NF; k0 += 16) {
        float4 a0 = *reinterpret_cast<const float4*>(&A[(size_t)(m0 + lr)      * NF + k0 + lc]);
        float4 a1 = *reinterpret_cast<const float4*>(&A[(size_t)(m0 + lr + 64) * NF + k0 + lc]);
        float4 b0 = *reinterpret_cast<const float4*>(&B[(size_t)(n0 + lr)      * NF + k0 + lc]);
        float4 b1 = *reinterpret_cast<const float4*>(&B[(size_t)(n0 + lr + 64) * NF + k0 + lc]);
        __syncthreads();
        As[(lc + 0) * LDA + lr] = a0.x; As[(lc + 1) * LDA + lr] = a0.y;
        As[(lc + 2) * LDA + lr] = a0.z; As[(lc + 3) * LDA + lr] = a0.w;
        As[(lc + 0) * LDA + lr + 64] = a1.x; As[(lc + 1) * LDA + lr + 64] = a1.y;
        As[(lc + 2) * LDA + lr + 64] = a1.z; As[(lc + 3) * LDA + lr + 64] = a1.w;
        Bs[(lc + 0) * LDA + lr] = b0.x; Bs[(lc + 1) * LDA + lr] = b0.y;
        Bs[(lc + 2) * LDA + lr] = b0.z; Bs[(lc + 3) * LDA + lr] = b0.w;
        Bs[(lc + 0) * LDA + lr + 64] = b1.x; Bs[(lc + 1) * LDA + lr + 64] = b1.y;
        Bs[(lc + 2) * LDA + lr + 64] = b1.z; Bs[(lc + 3) * LDA + lr + 64] = b1.w;
        __syncthreads();
#pragma unroll
        for (int k = 0; k < 16; k++) {
            ulonglong2 ap01 = *reinterpret_cast<const ulonglong2*>(&As[k * LDA + ty * 8]);
            ulonglong2 ap23 = *reinterpret_cast<const ulonglong2*>(&As[k * LDA + ty * 8 + 4]);
            unsigned long long ap[4] = {ap01.x, ap01.y, ap23.x, ap23.y};
            float4 bv0 = *reinterpret_cast<const float4*>(&Bs[k * LDA + tx * 8]);
            float4 bv1 = *reinterpret_cast<const float4*>(&Bs[k * LDA + tx * 8 + 4]);
            float bvals[8] = {bv0.x, bv0.y, bv0.z, bv0.w, bv1.x, bv1.y, bv1.z, bv1.w};
#pragma unroll
            for (int j = 0; j < 8; j++) {
                unsigned long long bb2 = splat2(bvals[j]);
#pragma unroll
                for (int ip = 0; ip < 4; ip++)
                    acc2[ip][j] = ffma2(ap[ip], bb2, acc2[ip][j]);
            }
        }
    }

#pragma unroll
    for (int ip = 0; ip < 4; ip++) {
        size_t row0 = (size_t)(m0 + ty * 8 + 2 * ip) * G4 + n0 + tx * 8;
        size_t row1 = row0 + G4;
#pragma unroll
        for (int j = 0; j < 8; j++) {
            float bj = bias[n0 + tx * 8 + j];
            C[row0 + j] = lo2(acc2[ip][j]) + bj;
            C[row1 + j] = hi2(acc2[ip][j]) + bj;
        }
    }
}

// ---------------- persistent recurrence kernel (R8 topology, unchanged) ------
__global__ void __launch_bounds__(256, 1) lstm_rec_kernel(
    const float* __restrict__ Whf, const float* __restrict__ Whb)
{
    extern __shared__ float smem[];
    float* ws = smem;                          // [SMEM_ROWS][1024]
    float* gv = smem + SMEM_ROWS * 1024;       // [64]
    float* cs = gv + 64;                       // [16]

    const int blk = blockIdx.x;
    const int dir = blk / NC_DIR;
    const int r   = blk % NC_DIR;
    const int h0 = (r * HID) / NC_DIR;
    const int h1 = ((r + 1) * HID) / NC_DIR;
    const int nh = h1 - h0;                    // 13 or 14
    const int R  = 4 * nh;

    const float* __restrict__ W = dir ? Whb : Whf;
    const int tid = threadIdx.x;
    const int lane = tid & 31, warp = tid >> 5;

    ulonglong2 wreg[REG_ROWS][8];
#pragma unroll
    for (int i = 0; i < REG_ROWS; i++) {
        int rl = warp + 8 * i;
        int gate = rl / nh;
        int j = rl - gate * nh;
        const float* wr = (rl < R) ? &W[(size_t)(gate * HID + h0 + j) * HID] : W;
#pragma unroll
        for (int k = 0; k < 8; k++)
            wreg[i][k] = *reinterpret_cast<const ulonglong2*>(wr + 4 * lane + 128 * k);
    }

    for (int idx = tid; idx < SMEM_ROWS * 256; idx += 256) {
        int rl = 40 + (idx >> 8);
        int c4 = (idx & 255) * 4;
        int gate = rl / nh;
        int j = rl - gate * nh;
        const float* wr = (rl < R) ? &W[(size_t)(gate * HID + h0 + j) * HID] : W;
        *reinterpret_cast<float4*>(&ws[(size_t)(rl - 40) * HID + c4]) =
            *reinterpret_cast<const float4*>(wr + c4);
    }
    if (tid < nh) cs[tid] = 0.0f;
    __syncthreads();

    unsigned int* ctr = &g_ctrs[dir * 64];

    for (int step = 0; step < T_SEQ; ++step) {
        const int t = dir ? (T_SEQ - 1 - step) : step;

        float xi = 0.f, xf = 0.f, xg = 0.f, xo = 0.f;
        if (tid < nh) {
            const float* xp = &g_xp[dir][(size_t)t * G4];
            xi = __ldg(&xp[h0 + tid]);
            xf = __ldg(&xp[HID + h0 + tid]);
            xg = __ldg(&xp[2 * HID + h0 + tid]);
            xo = __ldg(&xp[3 * HID + h0 + tid]);
        }

        if (step > 0) {
            if (tid == 0) {
                const unsigned int target = (unsigned int)(NC_DIR * step);
                while (ld_acquire_u32(ctr) < target) { }
            }
            __syncthreads();

            const float* hp = &g_hs[(size_t)(dir ? t + 1 : t - 1) * 2048 + dir * HID];
            ulonglong2 h2[8];
#pragma unroll
            for (int k = 0; k < 8; k++)
                h2[k] = __ldcg(reinterpret_cast<const ulonglong2*>(hp + 4 * lane + 128 * k));

            float a[RPW];
#pragma unroll
            for (int i = 0; i < REG_ROWS; i++) {
                unsigned long long s0 = 0ull, s1 = 0ull;
#pragma unroll
                for (int k = 0; k < 8; k++) {
                    s0 = ffma2(wreg[i][k].x, h2[k].x, s0);
                    s1 = ffma2(wreg[i][k].y, h2[k].y, s1);
                }
                a[i] = hsum2(s0) + hsum2(s1);
            }
#pragma unroll
            for (int i = REG_ROWS; i < RPW; i++) {
                const float* base = &ws[(size_t)(warp + 8 * i - 40) * HID + 4 * lane];
                unsigned long long s0 = 0ull, s1 = 0ull;
#pragma unroll
                for (int k = 0; k < 8; k++) {
                    ulonglong2 w2 = *reinterpret_cast<const ulonglong2*>(base + 128 * k);
                    s0 = ffma2(w2.x, h2[k].x, s0);
                    s1 = ffma2(w2.y, h2[k].y, s1);
                }
                a[i] = hsum2(s0) + hsum2(s1);
            }
#pragma unroll
            for (int off = 16; off > 0; off >>= 1)
#pragma unroll
                for (int i = 0; i < RPW; i++)
                    a[i] += __shfl_xor_sync(0xffffffffu, a[i], off);
            if (lane == 0) {
#pragma unroll
                for (int i = 0; i < RPW; i++) gv[warp + 8 * i] = a[i];
            }
        } else {
            if (tid < 64) gv[tid] = 0.0f;
        }
        __syncthreads();

        if (tid < nh) {
            int j = tid;
            float gi = gv[j]          + xi;
            float gf = gv[nh + j]     + xf;
            float gg = gv[2 * nh + j] + xg;
            float go = gv[3 * nh + j] + xo;
            float c = fast_sig(gf) * cs[j] + fast_sig(gi) * fast_tanh(gg);
            cs[j] = c;
            float h = fast_sig(go) * fast_tanh(c);
            g_hs[(size_t)t * 2048 + dir * HID + h0 + j] = h;
        }
        __syncthreads();                 // h stores happen-before tid0's release
        if (tid == 0) red_release_add(ctr, 1u);
    }
}

// ---------------- feats -------------------------------------------------------
__global__ void feats_kernel(const float* __restrict__ Wlin, const float* __restrict__ blin)
{
    const int t = blockIdx.x;
    const int warp = threadIdx.x >> 5;
    const int lane = threadIdx.x & 31;
    const float* h = &g_hs[(size_t)t * 2048];
    const float* w = &Wlin[(size_t)warp * 2048];
    float a0 = 0.f, a1 = 0.f, a2 = 0.f, a3 = 0.f;
#pragma unroll
    for (int k = 0; k < 16; k++) {
        float4 hv = *reinterpret_cast<const float4*>(h + 4 * lane + 128 * k);
        float4 wv = __ldg(reinterpret_cast<const float4*>(w + 4 * lane + 128 * k));
        a0 += hv.x * wv.x; a1 += hv.y * wv.y; a2 += hv.z * wv.z; a3 += hv.w * wv.w;
    }
    float a = (a0 + a1) + (a2 + a3);
#pragma unroll
    for (int off = 16; off > 0; off >>= 1)
        a += __shfl_xor_sync(0xffffffffu, a, off);
    if (lane == 0) g_feats[t * NTAGS + warp] = a + blin[warp];
}

// ---------------- Viterbi -----------------------------------------------------
__global__ void __launch_bounds__(256, 1) viterbi_kernel(
    const float* __restrict__ trans, float* __restrict__ out)
{
    extern __shared__ char vsm[];
    float* sf = (float*)vsm;
    unsigned char* bps  = (unsigned char*)(vsm + T_SEQ * NTAGS * 4);
    unsigned char* path = bps + T_SEQ * NTAGS;

    const int nv4 = T_SEQ * NTAGS / 4;
    for (int idx = threadIdx.x; idx < nv4; idx += 256)
        reinterpret_cast<float4*>(sf)[idx] = reinterpret_cast<const float4*>(g_feats)[idx];
    __syncthreads();

    if (threadIdx.x < 32) {
        const int lane = threadIdx.x;
        float trow[NTAGS];
        float fv;
        if (lane < NTAGS) {
#pragma unroll
            for (int i = 0; i < NTAGS; i++) trow[i] = trans[lane * NTAGS + i];
            fv = (lane == START_TAG) ? 0.0f : -10000.0f;
        } else {
#pragma unroll
            for (int i = 0; i < NTAGS; i++) trow[i] = 0.0f;
            fv = -1e30f;
        }

        for (int t = 0; t < T_SEQ; t++) {
            float feat = (lane < NTAGS) ? sf[t * NTAGS + lane] : 0.0f;
            float best = -3.0e38f; int bi = 0;
#pragma unroll
            for (int i = 0; i < NTAGS; i++) {
                float v = __shfl_sync(0xffffffffu, fv, i) + trow[i];
                if (v > best) { best = v; bi = i; }   // first-max tie rule
            }
            if (lane < NTAGS) bps[t * NTAGS + lane] = (unsigned char)bi;
            fv = best + feat;
        }

        float term = (lane < NTAGS) ? (fv + trans[STOP_TAG * NTAGS + lane]) : -3.0e38f;
        float bsc = -3.0e38f; int bidx = 0;
#pragma unroll
        for (int i = 0; i < NTAGS; i++) {
            float v = __shfl_sync(0xffffffffu, term, i);
            if (v > bsc) { bsc = v; bidx = i; }
        }

        if (lane == 0) {
            out[0] = bsc;
            int cur = bidx;
            path[T_SEQ - 1] = (unsigned char)cur;
            for (int t = T_SEQ - 2; t >= 0; --t) {
                cur = bps[(t + 1) * NTAGS + cur];
                path[t] = (unsigned char)cur;
            }
        }
        __syncwarp();
        for (int t = lane; t < T_SEQ; t += 32) out[1 + t] = (float)path[t];
    }
}

// ---------------- launch ------------------------------------------------------
extern "C" void kernel_launch(void* const* d_in, const int* in_sizes, int n_in,
                              void* d_out, int out_size)
{
    const float* sentence = (const float*)d_in[0];
    const float* W_ih_f   = (const float*)d_in[1];
    const float* W_hh_f   = (const float*)d_in[2];
    const float* b_f      = (const float*)d_in[3];
    const float* W_ih_b   = (const float*)d_in[4];
    const float* W_hh_b   = (const float*)d_in[5];
    const float* b_b      = (const float*)d_in[6];
    const float* W_lin    = (const float*)d_in[7];
    const float* b_lin    = (const float*)d_in[8];
    const float* trans    = (const float*)d_in[9];
    float* out = (float*)d_out;

    cudaFuncSetAttribute((const void*)lstm_rec_kernel,
                         cudaFuncAttributeMaxDynamicSharedMemorySize, REC_SMEM);
    cudaFuncSetAttribute((const void*)viterbi_kernel,
                         cudaFuncAttributeMaxDynamicSharedMemorySize, VIT_SMEM);

    // 3 tiny leading launches -> profiled (4th) launch = xp_gemm_kernel
    ctr_init_kernel<<<1, 1>>>();
    nop_kernel<<<1, 1>>>();
    nop_kernel<<<1, 1>>>();

    dim3 gg(G4 / 128, T_SEQ / 128, 2);
    xp_gemm_kernel<<<gg, 256>>>(sentence, W_ih_f, W_ih_b, b_f, b_b);

    lstm_rec_kernel<<<NCTA, 256, REC_SMEM>>>(W_hh_f, W_hh_b);

    feats_kernel<<<T_SEQ, NTAGS * 32>>>(W_lin, b_lin);

    viterbi_kernel<<<1, 256, VIT_SMEM>>>(trans, out);

    (void)in_sizes; (void)n_in; (void)out_size;
}